// round 2
// baseline (speedup 1.0000x reference)
#include <cuda_runtime.h>
#include <cuda_bf16.h>
#include <cstdint>

#define LV       4087
#define BROWS    2048
#define NSTEP    1021
#define NCH      4096
#define EPSF     1e-6f
#define CSTRIDE  4096
#define PADSTEP  1032

// 67.6 MB coefficient scratch, [step][chain] layout: {-l*ct, l*st*cos(chi), l*st*sin(chi), 0}
__device__ float4 g_coef[(size_t)PADSTEP * NCH];
__device__ float4 g_init[NCH];   // {bl0, -bl1*ct0, bl1*st0, 0}
__device__ double g_acc;

__device__ __forceinline__ float dnbl(float v) { return ((v + 1.0f) * 0.5f) * 2.1f + 0.9f; }
__device__ __forceinline__ float dnd (float v) { return ((v + 1.0f) * 0.5f) * 3.5f + 1.5f; }
__device__ __forceinline__ float clip1(float v) { return fminf(fmaxf(v, -1.0f), 1.0f); }

// ---------------------------------------------------------------------------
// Init: per-chain initial geometry (atoms 1,2) + zero the accumulator.
// ---------------------------------------------------------------------------
__global__ void init_kernel(const float* __restrict__ pred, const float* __restrict__ targ)
{
    int chain = blockIdx.x * blockDim.x + threadIdx.x;
    if (chain == 0) g_acc = 0.0;
    if (chain >= NCH) return;
    int row = chain & (BROWS - 1);
    bool isP = chain < BROWS;
    const float* v = (isP ? pred : targ) + (size_t)row * LV;

    float b0 = v[3064], b1 = v[3065], dr = v[2042];
    if (isP) { b0 = clip1(b0); b1 = clip1(b1); dr = clip1(dr); }
    float l1 = dnbl(b0), l2 = dnbl(b1), dd = dnd(dr);
    float ct = (l1 * l1 + l2 * l2 - dd * dd) / (2.0f * l1 * l2);
    ct = fminf(fmaxf(ct, -1.0f + EPSF), 1.0f - EPSF);
    float st = sqrtf((1.0f - ct) * (1.0f + ct));
    float4 o;
    o.x = l1;          // a1.x
    o.y = -l2 * ct;    // (a2-a1).x
    o.z =  l2 * st;    // (a2-a1).y
    o.w = 0.0f;
    g_init[chain] = o;
}

// ---------------------------------------------------------------------------
// Prep: per-(chain, step) scan coefficients. Trig removed analytically:
//   cos(theta)=ct (clipped), sin(theta)=sqrt((1-ct)(1+ct))  [cancellation-safe],
//   cos(chi)=sc1/h, sin(chi)=sc0/h.
// Block (32 chains x 32 steps); writes coalesced along chains.
// ---------------------------------------------------------------------------
__global__ __launch_bounds__(1024) void prep_kernel(const float* __restrict__ pred,
                                                    const float* __restrict__ targ)
{
    int c = blockIdx.x * 32 + threadIdx.x;   // chain 0..4095
    int j = blockIdx.y * 32 + threadIdx.y;   // step  0..1023
    if (j >= NSTEP) return;
    int row = c & (BROWS - 1);
    bool isP = c < BROWS;
    const float* v = (isP ? pred : targ) + (size_t)row * LV;

    float b1r = v[3064 + j + 1];
    float b2r = v[3064 + j + 2];
    float dr  = v[2042 + j + 1];
    float s0  = v[2 * j];
    float s1  = v[2 * j + 1];
    if (isP) {
        b1r = clip1(b1r); b2r = clip1(b2r); dr = clip1(dr);
        s0 = clip1(s0);   s1 = clip1(s1);
    }
    float l1 = dnbl(b1r), l = dnbl(b2r), dd = dnd(dr);
    float ct = (l1 * l1 + l * l - dd * dd) / (2.0f * l1 * l);
    ct = fminf(fmaxf(ct, -1.0f + EPSF), 1.0f - EPSF);
    float st = sqrtf((1.0f - ct) * (1.0f + ct));

    float h2 = s0 * s0 + s1 * s1;
    float cch, sch;
    if (h2 < 1e-30f) { cch = 1.0f; sch = 0.0f; }
    else { float rh = rsqrtf(h2); cch = s1 * rh; sch = s0 * rh; }

    float4 o;
    o.x = -l * ct;
    o.y =  l * st * cch;
    o.z =  l * st * sch;
    o.w = 0.0f;
    g_coef[(size_t)j * CSTRIDE + c] = o;
}

// ---------------------------------------------------------------------------
// Scan: one lane per chain. Lanes 0-15 = pred rows, 16-31 = targ same rows.
// Positions maintained and bonds recomputed from positions (matches reference
// rounding). Per-step shfl.bfly(16) pairs pred/targ for the loss.
// ---------------------------------------------------------------------------
__device__ __forceinline__ void step_fn(const float4 cf,
    float& ax, float& ay, float& az,
    float& bx, float& by, float& bz,
    float& cx, float& cy, float& cz,
    float& acc)
{
    float u1x = bx - ax, u1y = by - ay, u1z = bz - az;
    float u2x = cx - bx, u2y = cy - by, u2z = cz - bz;

    float A2  = fmaf(u2x, u2x, fmaf(u2y, u2y, u2z * u2z));
    float inv = __fdividef(1.0f, sqrtf(A2) + EPSF);
    float bcx = u2x * inv, bcy = u2y * inv, bcz = u2z * inv;

    float wx = u1y * bcz - u1z * bcy;
    float wy = u1z * bcx - u1x * bcz;
    float wz = u1x * bcy - u1y * bcx;
    float W2   = fmaf(wx, wx, fmaf(wy, wy, wz * wz));
    float invn = __fdividef(1.0f, sqrtf(W2) + EPSF);
    float nx = wx * invn, ny = wy * invn, nz = wz * invn;

    float mx = ny * bcz - nz * bcy;
    float my = nz * bcx - nx * bcz;
    float mz = nx * bcy - ny * bcx;

    float ex = fmaf(cf.x, bcx, fmaf(cf.y, mx, cf.z * nx));
    float ey = fmaf(cf.x, bcy, fmaf(cf.y, my, cf.z * ny));
    float ez = fmaf(cf.x, bcz, fmaf(cf.y, mz, cf.z * nz));

    float dx = cx + ex, dy = cy + ey, dz = cz + ez;
    ax = bx; ay = by; az = bz;
    bx = cx; by = cy; bz = cz;
    cx = dx; cy = dy; cz = dz;

    float ox = __shfl_xor_sync(0xffffffffu, dx, 16);
    float oy = __shfl_xor_sync(0xffffffffu, dy, 16);
    float oz = __shfl_xor_sync(0xffffffffu, dz, 16);
    float fx = dx - ox, fy = dy - oy, fz = dz - oz;
    acc = fmaf(fx, fx, acc);
    acc = fmaf(fy, fy, acc);
    acc = fmaf(fz, fz, acc);
}

__global__ void __launch_bounds__(32) scan_kernel()
{
    int lane  = threadIdx.x;
    int row   = blockIdx.x * 16 + (lane & 15);
    int chain = row + ((lane >> 4) << 11);   // +2048 for targ half

    float4 ini = g_init[chain];
    float ax = 0.f, ay = 0.f, az = 0.f;
    float bx = ini.x, by = 0.f, bz = 0.f;
    float cx = bx + ini.y, cy = ini.z, cz = 0.f;
    float acc = 0.f;

    // atoms 1 and 2 (atom 0 is identically zero on both sides)
    {
        float o1 = __shfl_xor_sync(0xffffffffu, bx, 16);
        float o2 = __shfl_xor_sync(0xffffffffu, cx, 16);
        float o3 = __shfl_xor_sync(0xffffffffu, cy, 16);
        float f1 = bx - o1, f2 = cx - o2, f3 = cy - o3;
        acc = fmaf(f1, f1, acc);
        acc = fmaf(f2, f2, acc);
        acc = fmaf(f3, f3, acc);
    }

    const float4* p = g_coef + chain;
    float4 buf[8];
#pragma unroll
    for (int u = 0; u < 8; ++u) buf[u] = __ldg(p + (size_t)u * CSTRIDE);

#pragma unroll 1
    for (int g = 0; g < 127; ++g) {          // 127*8 = 1016 steps
        const float4* pn = p + (size_t)8 * CSTRIDE;
#pragma unroll
        for (int u = 0; u < 8; ++u) {
            float4 cf = buf[u];
            buf[u] = __ldg(pn + (size_t)u * CSTRIDE);   // prefetch step j+8
            step_fn(cf, ax, ay, az, bx, by, bz, cx, cy, cz, acc);
        }
        p = pn;
    }
#pragma unroll
    for (int u = 0; u < 5; ++u)              // steps 1016..1020
        step_fn(buf[u], ax, ay, az, bx, by, bz, cx, cy, cz, acc);

    // warp reduce (halves hold identical values -> total is 2x true sum)
#pragma unroll
    for (int off = 16; off > 0; off >>= 1)
        acc += __shfl_xor_sync(0xffffffffu, acc, off);
    if (lane == 0) atomicAdd(&g_acc, (double)acc);
}

__global__ void fin_kernel(float* out)
{
    // divide by 2 (double counting) and by element count 2048*1024*3
    out[0] = (float)(g_acc * (1.0 / (2.0 * 2048.0 * 1024.0 * 3.0)));
}

extern "C" void kernel_launch(void* const* d_in, const int* in_sizes, int n_in,
                              void* d_out, int out_size)
{
    const float* pred = (const float*)d_in[0];
    const float* targ = (const float*)d_in[1];
    float* out = (float*)d_out;

    init_kernel<<<16, 256>>>(pred, targ);
    dim3 pb(32, 32), pg(NCH / 32, (NSTEP + 31) / 32);
    prep_kernel<<<pg, pb>>>(pred, targ);
    scan_kernel<<<BROWS / 16, 32>>>();
    fin_kernel<<<1, 1>>>(out);
}

// round 3
// speedup vs baseline: 3.1576x; 3.1576x over previous
#include <cuda_runtime.h>
#include <cuda_bf16.h>
#include <cstdint>

#define LV       4087
#define BROWS    2048
#define NSTEP    1021
#define NCH      4096
#define EPSF     1e-6f
#define CSTRIDE  4096
#define PADSTEP  1032

// 67.6 MB coefficient scratch, [step][chain]: {-l*ct, l*st*cos(chi), l*st*sin(chi), 0}
__device__ float4 g_coef[(size_t)PADSTEP * NCH];
__device__ float4 g_init[NCH];   // {l1, -l2*ct0, l2*st0, 0}
__device__ double g_acc;

__device__ __forceinline__ float dnbl(float v) { return ((v + 1.0f) * 0.5f) * 2.1f + 0.9f; }
__device__ __forceinline__ float dnd (float v) { return ((v + 1.0f) * 0.5f) * 3.5f + 1.5f; }
__device__ __forceinline__ float clip1(float v) { return fminf(fmaxf(v, -1.0f), 1.0f); }

__device__ __forceinline__ float rsq_approx(float x) {
    float y; asm("rsqrt.approx.f32 %0, %1;" : "=f"(y) : "f"(x)); return y;
}
__device__ __forceinline__ float rcp_approx(float x) {
    float y; asm("rcp.approx.f32 %0, %1;" : "=f"(y) : "f"(x)); return y;
}

// ---------------------------------------------------------------------------
// Init: per-chain initial geometry (atoms 1,2) + zero the accumulator.
// ---------------------------------------------------------------------------
__global__ void init_kernel(const float* __restrict__ pred, const float* __restrict__ targ)
{
    int chain = blockIdx.x * blockDim.x + threadIdx.x;
    if (chain == 0) g_acc = 0.0;
    if (chain >= NCH) return;
    int row = chain & (BROWS - 1);
    bool isP = chain < BROWS;
    const float* v = (isP ? pred : targ) + (size_t)row * LV;

    float b0 = v[3064], b1 = v[3065], dr = v[2042];
    if (isP) { b0 = clip1(b0); b1 = clip1(b1); dr = clip1(dr); }
    float l1 = dnbl(b0), l2 = dnbl(b1), dd = dnd(dr);
    float ct = (l1 * l1 + l2 * l2 - dd * dd) / (2.0f * l1 * l2);
    ct = fminf(fmaxf(ct, -1.0f + EPSF), 1.0f - EPSF);
    float st = sqrtf((1.0f - ct) * (1.0f + ct));
    float4 o;
    o.x = l1; o.y = -l2 * ct; o.z = l2 * st; o.w = 0.0f;
    g_init[chain] = o;
}

// ---------------------------------------------------------------------------
// Prep: lane = step (coalesced reads), smem transpose, coalesced writes.
// Block: 32 steps (x) x 32 chains (y). Grid: (32 j-tiles, 128 chain-tiles).
// ---------------------------------------------------------------------------
__global__ __launch_bounds__(1024) void prep_kernel(const float* __restrict__ pred,
                                                    const float* __restrict__ targ)
{
    __shared__ float4 T[32][33];
    const int tx = threadIdx.x;            // step offset in tile
    const int ty = threadIdx.y;            // chain offset in tile
    const int J0 = blockIdx.x * 32;
    const int C0 = blockIdx.y * 32;
    const int c  = C0 + ty;
    const int j  = J0 + tx;
    const int row = c & (BROWS - 1);
    const bool isP = c < BROWS;
    const float* __restrict__ v = (isP ? pred : targ) + (size_t)row * LV;

    float4 o = make_float4(0.f, 0.f, 0.f, 0.f);
    if (j < NSTEP) {
        float b1r = v[3064 + j + 1];
        float b2r = v[3064 + j + 2];
        float dr  = v[2042 + j + 1];
        float s0  = v[2 * j];
        float s1  = v[2 * j + 1];
        if (isP) {
            b1r = clip1(b1r); b2r = clip1(b2r); dr = clip1(dr);
            s0 = clip1(s0);   s1 = clip1(s1);
        }
        float l1 = dnbl(b1r), l = dnbl(b2r), dd = dnd(dr);
        float ct = (l1 * l1 + l * l - dd * dd) / (2.0f * l1 * l);
        ct = fminf(fmaxf(ct, -1.0f + EPSF), 1.0f - EPSF);
        float st = sqrtf((1.0f - ct) * (1.0f + ct));

        float h2 = s0 * s0 + s1 * s1;
        float cch, sch;
        if (h2 < 1e-30f) { cch = 1.0f; sch = 0.0f; }
        else { float rh = rsqrtf(h2); cch = s1 * rh; sch = s0 * rh; }

        o.x = -l * ct;
        o.y =  l * st * cch;
        o.z =  l * st * sch;
    }
    T[ty][tx] = o;
    __syncthreads();

    int jo = J0 + ty;                      // step for the write phase
    if (jo < 1024)
        g_coef[(size_t)jo * CSTRIDE + (C0 + tx)] = T[tx][ty];
}

// ---------------------------------------------------------------------------
// Scan: one lane per chain, bonds carried in registers, factored normalization:
//   w = u1 x bc = (u1 x u2)*inv1 ;  n = c12*(inv1*inv2) ; m = (c12 x u2)*(inv1^2*inv2)
//   e = s1*u2 + s2*(c12 x u2) + s3*c12
// with inv1 ~ 1/(|u2|+eps), inv2 ~ 1/(|w|+eps) via rsqrt/rcp.approx + eps fold.
// ---------------------------------------------------------------------------
__device__ __forceinline__ void step_fn(const float4 cf,
    float& u1x, float& u1y, float& u1z,
    float& u2x, float& u2y, float& u2z,
    float& cx, float& cy, float& cz,
    float& acc)
{
    float c12x = fmaf(u1y, u2z, -u1z * u2y);
    float c12y = fmaf(u1z, u2x, -u1x * u2z);
    float c12z = fmaf(u1x, u2y, -u1y * u2x);

    float cxux = fmaf(c12y, u2z, -c12z * u2y);
    float cxuy = fmaf(c12z, u2x, -c12x * u2z);
    float cxuz = fmaf(c12x, u2y, -c12y * u2x);

    float A2 = fmaf(u2x, u2x, fmaf(u2y, u2y, u2z * u2z));
    float C2 = fmaf(c12x, c12x, fmaf(c12y, c12y, c12z * c12z));

    float r1   = rsq_approx(A2);
    float inv1 = fmaf(-EPSF * r1, r1, r1);          // 1/(|u2|+eps)
    float rC   = rsq_approx(C2);
    float nw   = C2 * rC;                           // |c12|
    float inv2 = rcp_approx(fmaf(nw, inv1, EPSF));  // 1/(|w|+eps)

    float i12 = inv1 * inv2;
    float s1  = cf.x * inv1;
    float s3  = cf.z * i12;
    float s2  = cf.y * (i12 * inv1);

    float ex = fmaf(s1, u2x, fmaf(s2, cxux, s3 * c12x));
    float ey = fmaf(s1, u2y, fmaf(s2, cxuy, s3 * c12y));
    float ez = fmaf(s1, u2z, fmaf(s2, cxuz, s3 * c12z));

    float dx = cx + ex, dy = cy + ey, dz = cz + ez;
    u1x = u2x; u1y = u2y; u1z = u2z;
    u2x = ex;  u2y = ey;  u2z = ez;
    cx = dx;   cy = dy;   cz = dz;

    float ox = __shfl_xor_sync(0xffffffffu, dx, 16);
    float oy = __shfl_xor_sync(0xffffffffu, dy, 16);
    float oz = __shfl_xor_sync(0xffffffffu, dz, 16);
    float fx = dx - ox, fy = dy - oy, fz = dz - oz;
    acc = fmaf(fx, fx, acc);
    acc = fmaf(fy, fy, acc);
    acc = fmaf(fz, fz, acc);
}

__global__ void __launch_bounds__(32) scan_kernel()
{
    int lane  = threadIdx.x;
    int row   = blockIdx.x * 16 + (lane & 15);
    int chain = row + ((lane >> 4) << 11);   // +2048 for targ half

    float4 ini = g_init[chain];
    float u1x = ini.x, u1y = 0.f, u1z = 0.f;       // a1 - a0
    float u2x = ini.y, u2y = ini.z, u2z = 0.f;     // a2 - a1
    float cx = ini.x + ini.y, cy = ini.z, cz = 0.f;
    float acc = 0.f;

    // atoms 1 and 2 (atom 0 identical on both sides)
    {
        float o1 = __shfl_xor_sync(0xffffffffu, u1x, 16);
        float o2 = __shfl_xor_sync(0xffffffffu, cx, 16);
        float o3 = __shfl_xor_sync(0xffffffffu, cy, 16);
        float f1 = u1x - o1, f2 = cx - o2, f3 = cy - o3;
        acc = fmaf(f1, f1, acc);
        acc = fmaf(f2, f2, acc);
        acc = fmaf(f3, f3, acc);
    }

    const float4* p = g_coef + chain;
    float4 buf[8];
#pragma unroll
    for (int u = 0; u < 8; ++u) buf[u] = __ldg(p + (size_t)u * CSTRIDE);

#pragma unroll 1
    for (int g = 0; g < 127; ++g) {          // 127*8 = 1016 steps
        const float4* pn = p + (size_t)8 * CSTRIDE;
#pragma unroll
        for (int u = 0; u < 8; ++u) {
            float4 cf = buf[u];
            buf[u] = __ldg(pn + (size_t)u * CSTRIDE);
            step_fn(cf, u1x, u1y, u1z, u2x, u2y, u2z, cx, cy, cz, acc);
        }
        p = pn;
    }
#pragma unroll
    for (int u = 0; u < 5; ++u)              // steps 1016..1020
        step_fn(buf[u], u1x, u1y, u1z, u2x, u2y, u2z, cx, cy, cz, acc);

    // warp reduce (halves duplicated -> 2x true sum)
#pragma unroll
    for (int off = 16; off > 0; off >>= 1)
        acc += __shfl_xor_sync(0xffffffffu, acc, off);
    if (lane == 0) atomicAdd(&g_acc, (double)acc);
}

__global__ void fin_kernel(float* out)
{
    out[0] = (float)(g_acc * (1.0 / (2.0 * 2048.0 * 1024.0 * 3.0)));
}

extern "C" void kernel_launch(void* const* d_in, const int* in_sizes, int n_in,
                              void* d_out, int out_size)
{
    const float* pred = (const float*)d_in[0];
    const float* targ = (const float*)d_in[1];
    float* out = (float*)d_out;

    init_kernel<<<16, 256>>>(pred, targ);
    dim3 pb(32, 32), pg(32, NCH / 32);
    prep_kernel<<<pg, pb>>>(pred, targ);
    scan_kernel<<<BROWS / 16, 32>>>();
    fin_kernel<<<1, 1>>>(out);
}